// round 15
// baseline (speedup 1.0000x reference)
#include <cuda_runtime.h>
#include <math.h>

#define DD 64
#define KK 512
#define NV 65536
#define DECAYF 0.99f
#define EPSF 1e-5f

#define TPB   256
#define ROWT  64
#define XS    68            // x-tile row stride (floats), 16B-aligned
#define NTILES (NV / ROWT)  // 1024
#define GRID  152

// Output layout (concatenated float32, reference tuple order)
#define OFF_Q      0
#define OFF_LOSS   (NV * DD)
#define OFF_PERP   (OFF_LOSS + 1)
#define OFF_IDX    (OFF_PERP + 1)
#define OFF_NEWEMB (OFF_IDX + NV)
#define OFF_HIDCS  (OFF_NEWEMB + DD*KK)
#define OFF_HIDDW  (OFF_HIDCS + KK)

typedef unsigned long long ull;

// Packed fp32x2 FMA: 2 IEEE fp32 FMAs per instruction, bit-exact vs scalar fmaf.
__device__ __forceinline__ ull ffma2(ull a, ull b, ull c) {
    ull d;
    asm("fma.rn.f32x2 %0, %1, %2, %3;" : "=l"(d) : "l"(a), "l"(b), "l"(c));
    return d;
}
__device__ __forceinline__ ull pack2(float lo, float hi) {
    ull r;
    asm("mov.b64 %0, {%1, %2};" : "=l"(r) : "f"(lo), "f"(hi));
    return r;
}
__device__ __forceinline__ float2 unpack2(ull v) {
    float2 f;
    asm("mov.b64 {%0, %1}, %2;" : "=f"(f.x), "=f"(f.y) : "l"(v));
    return f;
}
// Monotonic float->uint key; idx in low 32 bits => u64-min == (min score, min idx)
__device__ __forceinline__ ull keyf(float s, unsigned idx) {
    unsigned u = __float_as_uint(s);
    u = (u & 0x80000000u) ? ~u : (u | 0x80000000u);
    return ((ull)u << 32) | (ull)idx;
}
__device__ __forceinline__ ull umin64(ull a, ull b) { return a < b ? a : b; }

// Scratch (device globals; zero-init at load, consumers restore zeros)
__device__ float g_dw[DD * KK];
__device__ float g_cs[KK];
__device__ float g_loss;
__device__ float g_inv_stable[KK];
__device__ float g_inv_debias;
__device__ ull   g_best[NV];          // winner key per row; fully rewritten every call
__device__ float g_eT[KK * DD];       // fp32 codebook transposed [k][d]; rewritten every call

// ---------- prep: transpose codebook for k_finish's gathers ----------
__global__ void k_prep_e(const float* __restrict__ emb) {
    int gid = blockIdx.x * 512 + threadIdx.x;        // 32768
    int d = gid >> 9, k = gid & 511;
    g_eT[k * DD + d] = emb[gid];                     // coalesced read
}

// ---------- pure argmin GEMM: winner key per row, nothing else ----------
__global__ void __launch_bounds__(TPB, 1) k_main(
    const float* __restrict__ x, const float* __restrict__ emb)
{
    extern __shared__ float sm[];
    float* es  = sm;                      // [64][512] codebook
    float* esq = sm + DD * KK;            // [512]
    float* xs  = esq + KK;                // [64][XS] x-tile, transposed

    const int t = threadIdx.x;
    const int w = t >> 5;       // warp 0..7 -> rows 8w..8w+7
    const int l = t & 31;       // lane -> code quads 4l, 128+4l (per half)

    // Stage codebook once (persistent blocks)
    {
        const float4* src = (const float4*)emb;
        float4* dst = (float4*)es;
        for (int i = t; i < DD * KK / 4; i += TPB) dst[i] = src[i];
    }
    __syncthreads();
    for (int k = t; k < KK; k += TPB) {
        float s = 0.0f;
        #pragma unroll
        for (int d = 0; d < DD; d++) {
            float v = es[d * KK + k];
            s = fmaf(v, v, s);
        }
        esq[k] = s;
    }
    __syncthreads();

    const ull M2 = pack2(-2.0f, -2.0f);

    for (int tile = blockIdx.x; tile < NTILES; tile += gridDim.x) {
        // --- load x-tile transposed: xs[d][row] ---
        #pragma unroll
        for (int i = 0; i < 4; i++) {
            int c   = t + TPB * i;          // 0..1023 float4 tasks
            int row = c >> 4;
            int dq  = (c & 15) * 4;
            float4 v = *(const float4*)(x + (size_t)(tile * ROWT + row) * DD + dq);
            xs[(dq + 0) * XS + row] = v.x;
            xs[(dq + 1) * XS + row] = v.y;
            xs[(dq + 2) * XS + row] = v.z;
            xs[(dq + 3) * XS + row] = v.w;
        }
        __syncthreads();

        ull best[8];
        #pragma unroll
        for (int r = 0; r < 8; r++) best[r] = ~0ull;

        #pragma unroll
        for (int h = 0; h < 2; h++) {
            const int cb = 256 * h;
            ull acc[8][4];
            #pragma unroll
            for (int r = 0; r < 8; r++)
                #pragma unroll
                for (int j = 0; j < 4; j++) acc[r][j] = 0ull;

            #pragma unroll 2
            for (int d = 0; d < DD; d++) {
                // broadcast: all lanes read this warp's 8 rows at dim d
                float4 a0 = *(const float4*)(xs + d * XS + 8 * w);
                float4 a1 = *(const float4*)(xs + d * XS + 8 * w + 4);
                // conflict-free: lane l -> code quad 4l (and 128+4l)
                ulonglong2 b0 = *(const ulonglong2*)(es + d * KK + cb + 4 * l);
                ulonglong2 b1 = *(const ulonglong2*)(es + d * KK + cb + 128 + 4 * l);
                ull ax0 = pack2(a0.x, a0.x), ax1 = pack2(a0.y, a0.y);
                ull ax2 = pack2(a0.z, a0.z), ax3 = pack2(a0.w, a0.w);
                ull ax4 = pack2(a1.x, a1.x), ax5 = pack2(a1.y, a1.y);
                ull ax6 = pack2(a1.z, a1.z), ax7 = pack2(a1.w, a1.w);
                ull ax[8] = {ax0, ax1, ax2, ax3, ax4, ax5, ax6, ax7};
                #pragma unroll
                for (int r = 0; r < 8; r++) {
                    acc[r][0] = ffma2(ax[r], b0.x, acc[r][0]);
                    acc[r][1] = ffma2(ax[r], b0.y, acc[r][1]);
                    acc[r][2] = ffma2(ax[r], b1.x, acc[r][2]);
                    acc[r][3] = ffma2(ax[r], b1.y, acc[r][3]);
                }
            }
            // scores: s = ||e||^2 - 2 x.e  (||x||^2 const per row; argmin-safe)
            ulonglong2 eq0 = *(const ulonglong2*)(esq + cb + 4 * l);
            ulonglong2 eq1 = *(const ulonglong2*)(esq + cb + 128 + 4 * l);
            const unsigned c0 = cb + 4 * l, c1 = cb + 128 + 4 * l;
            #pragma unroll
            for (int r = 0; r < 8; r++) {
                float2 s0 = unpack2(ffma2(M2, acc[r][0], eq0.x));
                float2 s1 = unpack2(ffma2(M2, acc[r][1], eq0.y));
                float2 s2 = unpack2(ffma2(M2, acc[r][2], eq1.x));
                float2 s3 = unpack2(ffma2(M2, acc[r][3], eq1.y));
                best[r] = umin64(best[r], keyf(s0.x, c0 + 0));
                best[r] = umin64(best[r], keyf(s0.y, c0 + 1));
                best[r] = umin64(best[r], keyf(s1.x, c0 + 2));
                best[r] = umin64(best[r], keyf(s1.y, c0 + 3));
                best[r] = umin64(best[r], keyf(s2.x, c1 + 0));
                best[r] = umin64(best[r], keyf(s2.y, c1 + 1));
                best[r] = umin64(best[r], keyf(s3.x, c1 + 2));
                best[r] = umin64(best[r], keyf(s3.y, c1 + 3));
            }
        }

        // cross-lane argmin per row; single-writer plain store (no atomics)
        #pragma unroll
        for (int r = 0; r < 8; r++) {
            #pragma unroll
            for (int off = 16; off; off >>= 1) {
                ull o = __shfl_xor_sync(0xffffffffu, best[r], off);
                best[r] = umin64(best[r], o);
            }
        }
        if (l == 0) {
            #pragma unroll
            for (int r = 0; r < 8; r++)
                g_best[tile * ROWT + 8 * w + r] = best[r];
        }
        __syncthreads();   // xs reuse barrier for next tile
    }
}

// ---------- winners -> idx, quantized, loss, cs/dw (memory-parallel) ----------
__global__ void __launch_bounds__(256) k_finish(
    const float* __restrict__ x, float* __restrict__ out)
{
    int r = blockIdx.x * 256 + threadIdx.x;      // 0..NV-1
    ull key = g_best[r];
    unsigned bi = (unsigned)(key & 0xffffffffull);

    out[OFF_IDX + r] = (float)bi;
    atomicAdd(&g_cs[bi], 1.0f);

    const float4* xv = (const float4*)(x + (size_t)r * DD);
    const float4* ev = (const float4*)(g_eT + (size_t)bi * DD);
    float4* qv = (float4*)(out + OFF_Q + (size_t)r * DD);

    float lacc = 0.0f;
    #pragma unroll
    for (int i = 0; i < DD / 4; i++) {
        float4 xq = xv[i];
        float4 eq = ev[i];
        qv[i] = eq;
        float e0 = eq.x - xq.x, e1 = eq.y - xq.y;
        float e2 = eq.z - xq.z, e3 = eq.w - xq.w;
        lacc = fmaf(e0, e0, lacc); lacc = fmaf(e1, e1, lacc);
        lacc = fmaf(e2, e2, lacc); lacc = fmaf(e3, e3, lacc);
        atomicAdd(&g_dw[(4 * i + 0) * KK + bi], xq.x);
        atomicAdd(&g_dw[(4 * i + 1) * KK + bi], xq.y);
        atomicAdd(&g_dw[(4 * i + 2) * KK + bi], xq.z);
        atomicAdd(&g_dw[(4 * i + 3) * KK + bi], xq.w);
    }
    #pragma unroll
    for (int off = 16; off; off >>= 1)
        lacc += __shfl_down_sync(0xffffffffu, lacc, off);
    if ((threadIdx.x & 31) == 0) atomicAdd(&g_loss, lacc);
}

// --- epilogue part 1: per-code stats, fp32 fast path (1 block, 512 threads) ---
__global__ void k_fin1(const float* __restrict__ ema_cs,
                       const int* __restrict__ counter,
                       float* __restrict__ out)
{
    __shared__ float s_part[16];
    __shared__ float s_bcast[2];           // [0]=inv_debias, [1]=reduced scalar
    const int t = threadIdx.x;             // 512 == KK
    const int w = t >> 5, l = t & 31;

    if (t == 0) {
        double db = 1.0 - pow(0.99, (double)(counter[0] + 1));
        float invdb = (float)(1.0 / db);
        s_bcast[0] = invdb;
        g_inv_debias = invdb;
        out[OFF_LOSS] = 0.25f * (g_loss / (float)(NV * DD));
        g_loss = 0.0f;
    }
    __syncthreads();
    const float inv_db = s_bcast[0];

    float cs  = g_cs[t];
    g_cs[t] = 0.0f;                        // restore scratch
    float hid = ema_cs[t] * DECAYF + cs * (1.0f - DECAYF);
    out[OFF_HIDCS + t] = hid;
    float upd = hid * inv_db;

    // nsum = sum(upd)
    float v = upd;
    #pragma unroll
    for (int off = 16; off; off >>= 1) v += __shfl_xor_sync(0xffffffffu, v, off);
    if (l == 0) s_part[w] = v;
    __syncthreads();
    if (t < 32) {
        float pv = (t < 16) ? s_part[t] : 0.0f;
        #pragma unroll
        for (int off = 8; off; off >>= 1) pv += __shfl_xor_sync(0xffffffffu, pv, off);
        if (t == 0) s_bcast[1] = pv;
    }
    __syncthreads();
    const float nsum = s_bcast[1];

    float stable = ((upd + EPSF) / (nsum + (float)KK * EPSF)) * nsum;
    g_inv_stable[t] = 1.0f / stable;

    // entropy -> perplexity
    float p = cs * (1.0f / (float)NV);
    float e = -p * logf(p + 1e-10f);
    #pragma unroll
    for (int off = 16; off; off >>= 1) e += __shfl_xor_sync(0xffffffffu, e, off);
    if (l == 0) s_part[w] = e;
    __syncthreads();
    if (t < 32) {
        float pv = (t < 16) ? s_part[t] : 0.0f;
        #pragma unroll
        for (int off = 8; off; off >>= 1) pv += __shfl_xor_sync(0xffffffffu, pv, off);
        if (t == 0) out[OFF_PERP] = expf(pv);
    }
}

// --- epilogue part 2: 32K-element elementwise map, fp32 only, many blocks ---
__global__ void k_fin2(const float* __restrict__ ema_dw,
                       float* __restrict__ out)
{
    int i = blockIdx.x * blockDim.x + threadIdx.x;   // 64 x 512 = 32768
    float inv_deb = g_inv_debias;
    float dwv = g_dw[i];
    g_dw[i] = 0.0f;                       // restore scratch
    float hdw = ema_dw[i] * DECAYF + dwv * (1.0f - DECAYF);
    out[OFF_HIDDW + i] = hdw;
    out[OFF_NEWEMB + i] = (hdw * inv_deb) * g_inv_stable[i & (KK - 1)];
}

extern "C" void kernel_launch(void* const* d_in, const int* in_sizes, int n_in,
                              void* d_out, int out_size)
{
    const float* x       = (const float*)d_in[0];
    const float* emb     = (const float*)d_in[1];
    const float* ema_cs  = (const float*)d_in[2];
    const float* ema_dw  = (const float*)d_in[3];
    const int*   counter = (const int*)d_in[4];
    float* out = (float*)d_out;

    const int smem = (DD * KK + KK + DD * XS) * (int)sizeof(float);  // 150,528 B
    cudaFuncSetAttribute(k_main, cudaFuncAttributeMaxDynamicSharedMemorySize, smem);

    k_prep_e<<<64, 512>>>(emb);
    k_main<<<GRID, TPB, smem>>>(x, emb);
    k_finish<<<NV / 256, 256>>>(x, out);
    k_fin1<<<1, KK>>>(ema_cs, counter, out);
    k_fin2<<<64, 512>>>(ema_dw, out);
}

// round 16
// speedup vs baseline: 1.1720x; 1.1720x over previous
#include <cuda_runtime.h>
#include <math.h>

#define DD 64
#define KK 512
#define NV 65536
#define DECAYF 0.99f
#define EPSF 1e-5f

#define TPB   256
#define ROWT  64
#define XS    68            // x-tile row stride (floats), 16B-aligned
#define NTILES (NV / ROWT)  // 1024
#define GRID  152

// Output layout (concatenated float32, reference tuple order)
#define OFF_Q      0
#define OFF_LOSS   (NV * DD)
#define OFF_PERP   (OFF_LOSS + 1)
#define OFF_IDX    (OFF_PERP + 1)
#define OFF_NEWEMB (OFF_IDX + NV)
#define OFF_HIDCS  (OFF_NEWEMB + DD*KK)
#define OFF_HIDDW  (OFF_HIDCS + KK)

typedef unsigned long long ull;

// Packed fp32x2 FMA: 2 IEEE fp32 FMAs per instruction, bit-exact vs scalar fmaf.
__device__ __forceinline__ ull ffma2(ull a, ull b, ull c) {
    ull d;
    asm("fma.rn.f32x2 %0, %1, %2, %3;" : "=l"(d) : "l"(a), "l"(b), "l"(c));
    return d;
}
__device__ __forceinline__ ull pack2(float lo, float hi) {
    ull r;
    asm("mov.b64 %0, {%1, %2};" : "=l"(r) : "f"(lo), "f"(hi));
    return r;
}
__device__ __forceinline__ float2 unpack2(ull v) {
    float2 f;
    asm("mov.b64 {%0, %1}, %2;" : "=f"(f.x), "=f"(f.y) : "l"(v));
    return f;
}

// Scratch (device globals; zero-init at load, fin kernels restore zeros)
__device__ float g_dw[DD * KK];
__device__ float g_cs[KK];
__device__ float g_loss;
__device__ float g_inv_stable[KK];
__device__ float g_inv_debias;

__global__ void __launch_bounds__(TPB, 1) k_main(
    const float* __restrict__ x, const float* __restrict__ emb,
    float* __restrict__ out)
{
    extern __shared__ float sm[];
    float* es    = sm;                      // [64][512] codebook
    float* esq   = sm + DD * KK;            // [512]
    float* xs    = esq + KK;                // [64][XS] x-tile, transposed
    int*   sbidx = (int*)(xs + DD * XS);    // [64]

    const int t = threadIdx.x;
    const int w = t >> 5;       // warp 0..7 -> rows 8w..8w+7
    const int l = t & 31;       // lane -> code quads 4l + 128q, q=0..3

    // Stage codebook once (persistent blocks)
    {
        const float4* src = (const float4*)emb;
        float4* dst = (float4*)es;
        for (int i = t; i < DD * KK / 4; i += TPB) dst[i] = src[i];
    }
    __syncthreads();
    for (int k = t; k < KK; k += TPB) {
        float s = 0.0f;
        #pragma unroll
        for (int d = 0; d < DD; d++) {
            float v = es[d * KK + k];
            s = fmaf(v, v, s);
        }
        esq[k] = s;
    }
    __syncthreads();

    const ull M2 = pack2(-2.0f, -2.0f);
    float lacc = 0.0f;

    // esq for this lane's 16 codes (tile-invariant)
    ull eqa[8];
    {
        ulonglong2 e0 = *(const ulonglong2*)(esq + 4 * l);
        ulonglong2 e1 = *(const ulonglong2*)(esq + 128 + 4 * l);
        ulonglong2 e2 = *(const ulonglong2*)(esq + 256 + 4 * l);
        ulonglong2 e3 = *(const ulonglong2*)(esq + 384 + 4 * l);
        eqa[0] = e0.x; eqa[1] = e0.y; eqa[2] = e1.x; eqa[3] = e1.y;
        eqa[4] = e2.x; eqa[5] = e2.y; eqa[6] = e3.x; eqa[7] = e3.y;
    }

    for (int tile = blockIdx.x; tile < NTILES; tile += gridDim.x) {
        // --- load x-tile transposed: xs[d][row] ---
        #pragma unroll
        for (int i = 0; i < 4; i++) {
            int c   = t + TPB * i;          // 0..1023 float4 tasks
            int row = c >> 4;
            int dq  = (c & 15) * 4;
            float4 v = *(const float4*)(x + (size_t)(tile * ROWT + row) * DD + dq);
            xs[(dq + 0) * XS + row] = v.x;
            xs[(dq + 1) * XS + row] = v.y;
            xs[(dq + 2) * XS + row] = v.z;
            xs[(dq + 3) * XS + row] = v.w;
        }
        __syncthreads();

        // --- single pass over all 512 codes: acc[row][codegroup] ---
        ull acc[8][8];
        #pragma unroll
        for (int r = 0; r < 8; r++)
            #pragma unroll
            for (int g = 0; g < 8; g++) acc[r][g] = 0ull;

        #pragma unroll 1
        for (int d = 0; d < DD; d++) {
            float4 a0 = *(const float4*)(xs + d * XS + 8 * w);
            float4 a1 = *(const float4*)(xs + d * XS + 8 * w + 4);
            ulonglong2 b0 = *(const ulonglong2*)(es + d * KK + 4 * l);
            ulonglong2 b1 = *(const ulonglong2*)(es + d * KK + 128 + 4 * l);
            ulonglong2 b2 = *(const ulonglong2*)(es + d * KK + 256 + 4 * l);
            ulonglong2 b3 = *(const ulonglong2*)(es + d * KK + 384 + 4 * l);
            ull ax[8] = {pack2(a0.x, a0.x), pack2(a0.y, a0.y),
                         pack2(a0.z, a0.z), pack2(a0.w, a0.w),
                         pack2(a1.x, a1.x), pack2(a1.y, a1.y),
                         pack2(a1.z, a1.z), pack2(a1.w, a1.w)};
            ull bb[8] = {b0.x, b0.y, b1.x, b1.y, b2.x, b2.y, b3.x, b3.y};
            #pragma unroll
            for (int r = 0; r < 8; r++)
                #pragma unroll
                for (int g = 0; g < 8; g++)
                    acc[r][g] = ffma2(ax[r], bb[g], acc[r][g]);
        }

        // --- tail: scores, exact argmin, winner publication ---
        #pragma unroll
        for (int r = 0; r < 8; r++) {
            float s[16];
            #pragma unroll
            for (int g = 0; g < 8; g++) {
                float2 p = unpack2(ffma2(M2, acc[r][g], eqa[g]));
                s[2 * g]     = p.x;
                s[2 * g + 1] = p.y;
            }
            // lane min (15 FMNMX)
            float m = s[0];
            #pragma unroll
            for (int j = 1; j < 16; j++) m = fminf(m, s[j]);
            // row min across lanes
            #pragma unroll
            for (int off = 16; off; off >>= 1)
                m = fminf(m, __shfl_xor_sync(0xffffffffu, m, off));
            // exact index: min code among scores equal to row min
            // code_j = (j>>2)*128 + 4*l + (j&3); descending scan keeps smallest j
            int cand = 0x7fffffff;
            #pragma unroll
            for (int j = 15; j >= 0; j--)
                cand = (s[j] == m) ? ((j >> 2) * 128 + 4 * l + (j & 3)) : cand;
            #pragma unroll
            for (int off = 16; off; off >>= 1)
                cand = min(cand, __shfl_xor_sync(0xffffffffu, cand, off));
            if (l == 0) {
                sbidx[8 * w + r] = cand;
                out[OFF_IDX + tile * ROWT + 8 * w + r] = (float)cand;
                atomicAdd(&g_cs[cand], 1.0f);
            }
        }
        __syncthreads();

        // --- epilogue: quantized gather, loss, dw scatter ---
        #pragma unroll
        for (int i = 0; i < 4; i++) {
            int c   = t + TPB * i;
            int row = c & 63;
            int d4  = (c >> 6) * 4;
            int bi  = sbidx[row];
            float q0 = es[(d4 + 0) * KK + bi];
            float q1 = es[(d4 + 1) * KK + bi];
            float q2 = es[(d4 + 2) * KK + bi];
            float q3 = es[(d4 + 3) * KK + bi];
            float x0 = xs[(d4 + 0) * XS + row];
            float x1 = xs[(d4 + 1) * XS + row];
            float x2 = xs[(d4 + 2) * XS + row];
            float x3 = xs[(d4 + 3) * XS + row];
            float e0 = q0 - x0, e1 = q1 - x1, e2 = q2 - x2, e3 = q3 - x3;
            lacc = fmaf(e0, e0, lacc); lacc = fmaf(e1, e1, lacc);
            lacc = fmaf(e2, e2, lacc); lacc = fmaf(e3, e3, lacc);
            *(float4*)(out + OFF_Q + (size_t)(tile * ROWT + row) * DD + d4)
                = make_float4(q0, q1, q2, q3);
            atomicAdd(&g_dw[(d4 + 0) * KK + bi], x0);
            atomicAdd(&g_dw[(d4 + 1) * KK + bi], x1);
            atomicAdd(&g_dw[(d4 + 2) * KK + bi], x2);
            atomicAdd(&g_dw[(d4 + 3) * KK + bi], x3);
        }
        __syncthreads();
    }

    // loss: warp-reduce then one atomic per warp
    #pragma unroll
    for (int off = 16; off; off >>= 1)
        lacc += __shfl_down_sync(0xffffffffu, lacc, off);
    if (l == 0 && lacc != 0.0f) atomicAdd(&g_loss, lacc);
}

// --- epilogue part 1: per-code stats, fp32 fast path (1 block, 512 threads) ---
__global__ void k_fin1(const float* __restrict__ ema_cs,
                       const int* __restrict__ counter,
                       float* __restrict__ out)
{
    __shared__ float s_part[16];
    __shared__ float s_bcast[2];           // [0]=inv_debias, [1]=reduced scalar
    const int t = threadIdx.x;             // 512 == KK
    const int w = t >> 5, l = t & 31;

    if (t == 0) {
        double db = 1.0 - pow(0.99, (double)(counter[0] + 1));
        float invdb = (float)(1.0 / db);
        s_bcast[0] = invdb;
        g_inv_debias = invdb;
        out[OFF_LOSS] = 0.25f * (g_loss / (float)(NV * DD));
        g_loss = 0.0f;
    }
    __syncthreads();
    const float inv_db = s_bcast[0];

    float cs  = g_cs[t];
    g_cs[t] = 0.0f;                        // restore scratch
    float hid = ema_cs[t] * DECAYF + cs * (1.0f - DECAYF);
    out[OFF_HIDCS + t] = hid;
    float upd = hid * inv_db;

    // nsum = sum(upd)
    float v = upd;
    #pragma unroll
    for (int off = 16; off; off >>= 1) v += __shfl_xor_sync(0xffffffffu, v, off);
    if (l == 0) s_part[w] = v;
    __syncthreads();
    if (t < 32) {
        float pv = (t < 16) ? s_part[t] : 0.0f;
        #pragma unroll
        for (int off = 8; off; off >>= 1) pv += __shfl_xor_sync(0xffffffffu, pv, off);
        if (t == 0) s_bcast[1] = pv;
    }
    __syncthreads();
    const float nsum = s_bcast[1];

    float stable = ((upd + EPSF) / (nsum + (float)KK * EPSF)) * nsum;
    g_inv_stable[t] = 1.0f / stable;

    // entropy -> perplexity
    float p = cs * (1.0f / (float)NV);
    float e = -p * logf(p + 1e-10f);
    #pragma unroll
    for (int off = 16; off; off >>= 1) e += __shfl_xor_sync(0xffffffffu, e, off);
    if (l == 0) s_part[w] = e;
    __syncthreads();
    if (t < 32) {
        float pv = (t < 16) ? s_part[t] : 0.0f;
        #pragma unroll
        for (int off = 8; off; off >>= 1) pv += __shfl_xor_sync(0xffffffffu, pv, off);
        if (t == 0) out[OFF_PERP] = expf(pv);
    }
}

// --- epilogue part 2: 32K-element elementwise map, fp32 only, many blocks ---
__global__ void k_fin2(const float* __restrict__ ema_dw,
                       float* __restrict__ out)
{
    int i = blockIdx.x * blockDim.x + threadIdx.x;   // 64 x 512 = 32768
    float inv_deb = g_inv_debias;
    float dwv = g_dw[i];
    g_dw[i] = 0.0f;                       // restore scratch
    float hdw = ema_dw[i] * DECAYF + dwv * (1.0f - DECAYF);
    out[OFF_HIDDW + i] = hdw;
    out[OFF_NEWEMB + i] = (hdw * inv_deb) * g_inv_stable[i & (KK - 1)];
}

extern "C" void kernel_launch(void* const* d_in, const int* in_sizes, int n_in,
                              void* d_out, int out_size)
{
    const float* x       = (const float*)d_in[0];
    const float* emb     = (const float*)d_in[1];
    const float* ema_cs  = (const float*)d_in[2];
    const float* ema_dw  = (const float*)d_in[3];
    const int*   counter = (const int*)d_in[4];
    float* out = (float*)d_out;

    const int smem = (DD * KK + KK + DD * XS) * (int)sizeof(float)
                   + ROWT * (int)sizeof(int);        // 150,784 B
    cudaFuncSetAttribute(k_main, cudaFuncAttributeMaxDynamicSharedMemorySize, smem);

    k_main<<<GRID, TPB, smem>>>(x, emb, out);
    k_fin1<<<1, KK>>>(ema_cs, counter, out);
    k_fin2<<<64, 512>>>(ema_dw, out);
}

// round 17
// speedup vs baseline: 1.2294x; 1.0490x over previous
#include <cuda_runtime.h>
#include <math.h>

#define DD 64
#define KK 512
#define NV 65536
#define DECAYF 0.99f
#define EPSF 1e-5f

#define TPB   256
#define ROWT  64
#define XS    68          // x-tile row stride (floats), 16B-aligned
#define NTILES (NV / ROWT)  // 1024
#define GRID  152

// Output layout (concatenated float32, reference tuple order)
#define OFF_Q      0
#define OFF_LOSS   (NV * DD)
#define OFF_PERP   (OFF_LOSS + 1)
#define OFF_IDX    (OFF_PERP + 1)
#define OFF_NEWEMB (OFF_IDX + NV)
#define OFF_HIDCS  (OFF_NEWEMB + DD*KK)
#define OFF_HIDDW  (OFF_HIDCS + KK)

typedef unsigned long long ull;

// Packed fp32x2 FMA: 2 IEEE fp32 FMAs per instruction, bit-exact vs scalar fmaf.
__device__ __forceinline__ ull ffma2(ull a, ull b, ull c) {
    ull d;
    asm("fma.rn.f32x2 %0, %1, %2, %3;" : "=l"(d) : "l"(a), "l"(b), "l"(c));
    return d;
}
__device__ __forceinline__ ull pack2(float lo, float hi) {
    ull r;
    asm("mov.b64 %0, {%1, %2};" : "=l"(r) : "f"(lo), "f"(hi));
    return r;
}
__device__ __forceinline__ float2 unpack2(ull v) {
    float2 f;
    asm("mov.b64 {%0, %1}, %2;" : "=f"(f.x), "=f"(f.y) : "l"(v));
    return f;
}
// Monotonic float->uint key; idx in low 32 bits => u64-min == (min score, min idx)
__device__ __forceinline__ ull keyf(float s, unsigned idx) {
    unsigned u = __float_as_uint(s);
    u = (u & 0x80000000u) ? ~u : (u | 0x80000000u);
    return ((ull)u << 32) | (ull)idx;
}
__device__ __forceinline__ ull umin64(ull a, ull b) { return a < b ? a : b; }

// Scratch (device globals; zero-init at load, fin kernels restore zeros)
__device__ float g_dw[DD * KK];
__device__ float g_cs[KK];
__device__ float g_loss;
__device__ float g_inv_stable[KK];
__device__ float g_inv_debias;

__global__ void __launch_bounds__(TPB, 1) k_main(
    const float* __restrict__ x, const float* __restrict__ emb,
    float* __restrict__ out)
{
    extern __shared__ float sm[];
    float* es    = sm;                      // [64][512] codebook
    float* esq   = sm + DD * KK;            // [512]
    float* xs    = esq + KK;                // [64][XS] x-tile, transposed
    int*   sbidx = (int*)(xs + DD * XS);    // [64]

    const int t = threadIdx.x;
    const int w = t >> 5;       // warp 0..7 -> rows 8w..8w+7
    const int l = t & 31;       // lane -> code quads 4l, 128+4l (per half)

    // Stage codebook once (persistent blocks)
    {
        const float4* src = (const float4*)emb;
        float4* dst = (float4*)es;
        for (int i = t; i < DD * KK / 4; i += TPB) dst[i] = src[i];
    }
    __syncthreads();
    for (int k = t; k < KK; k += TPB) {
        float s = 0.0f;
        #pragma unroll
        for (int d = 0; d < DD; d++) {
            float v = es[d * KK + k];
            s = fmaf(v, v, s);
        }
        esq[k] = s;
    }
    __syncthreads();

    const ull M2 = pack2(-2.0f, -2.0f);
    float lacc = 0.0f;

    for (int tile = blockIdx.x; tile < NTILES; tile += gridDim.x) {
        // --- load x-tile transposed: xs[d][row] ---
        #pragma unroll
        for (int i = 0; i < 4; i++) {
            int c   = t + TPB * i;          // 0..1023 float4 tasks
            int row = c >> 4;
            int dq  = (c & 15) * 4;
            float4 v = *(const float4*)(x + (size_t)(tile * ROWT + row) * DD + dq);
            xs[(dq + 0) * XS + row] = v.x;
            xs[(dq + 1) * XS + row] = v.y;
            xs[(dq + 2) * XS + row] = v.z;
            xs[(dq + 3) * XS + row] = v.w;
        }
        __syncthreads();

        ull best[8];
        #pragma unroll
        for (int r = 0; r < 8; r++) best[r] = ~0ull;

        #pragma unroll
        for (int h = 0; h < 2; h++) {
            const int cb = 256 * h;
            ull acc[8][4];
            #pragma unroll
            for (int r = 0; r < 8; r++)
                #pragma unroll
                for (int j = 0; j < 4; j++) acc[r][j] = 0ull;

            #pragma unroll 2
            for (int d = 0; d < DD; d++) {
                // broadcast: all lanes read this warp's 8 rows at dim d
                float4 a0 = *(const float4*)(xs + d * XS + 8 * w);
                float4 a1 = *(const float4*)(xs + d * XS + 8 * w + 4);
                // conflict-free: lane l -> code quad 4l (and 128+4l)
                ulonglong2 b0 = *(const ulonglong2*)(es + d * KK + cb + 4 * l);
                ulonglong2 b1 = *(const ulonglong2*)(es + d * KK + cb + 128 + 4 * l);
                ull ax0 = pack2(a0.x, a0.x), ax1 = pack2(a0.y, a0.y);
                ull ax2 = pack2(a0.z, a0.z), ax3 = pack2(a0.w, a0.w);
                ull ax4 = pack2(a1.x, a1.x), ax5 = pack2(a1.y, a1.y);
                ull ax6 = pack2(a1.z, a1.z), ax7 = pack2(a1.w, a1.w);
                ull ax[8] = {ax0, ax1, ax2, ax3, ax4, ax5, ax6, ax7};
                #pragma unroll
                for (int r = 0; r < 8; r++) {
                    acc[r][0] = ffma2(ax[r], b0.x, acc[r][0]);
                    acc[r][1] = ffma2(ax[r], b0.y, acc[r][1]);
                    acc[r][2] = ffma2(ax[r], b1.x, acc[r][2]);
                    acc[r][3] = ffma2(ax[r], b1.y, acc[r][3]);
                }
            }
            // scores: s = ||e||^2 - 2 x.e  (||x||^2 const per row; argmin-safe)
            ulonglong2 eq0 = *(const ulonglong2*)(esq + cb + 4 * l);
            ulonglong2 eq1 = *(const ulonglong2*)(esq + cb + 128 + 4 * l);
            const unsigned c0 = cb + 4 * l, c1 = cb + 128 + 4 * l;
            #pragma unroll
            for (int r = 0; r < 8; r++) {
                float2 s0 = unpack2(ffma2(M2, acc[r][0], eq0.x));
                float2 s1 = unpack2(ffma2(M2, acc[r][1], eq0.y));
                float2 s2 = unpack2(ffma2(M2, acc[r][2], eq1.x));
                float2 s3 = unpack2(ffma2(M2, acc[r][3], eq1.y));
                best[r] = umin64(best[r], keyf(s0.x, c0 + 0));
                best[r] = umin64(best[r], keyf(s0.y, c0 + 1));
                best[r] = umin64(best[r], keyf(s1.x, c0 + 2));
                best[r] = umin64(best[r], keyf(s1.y, c0 + 3));
                best[r] = umin64(best[r], keyf(s2.x, c1 + 0));
                best[r] = umin64(best[r], keyf(s2.y, c1 + 1));
                best[r] = umin64(best[r], keyf(s3.x, c1 + 2));
                best[r] = umin64(best[r], keyf(s3.y, c1 + 3));
            }
        }

        // cross-lane argmin per row (u64 min keeps exact first-occurrence tie-break)
        #pragma unroll
        for (int r = 0; r < 8; r++) {
            #pragma unroll
            for (int off = 16; off; off >>= 1) {
                ull o = __shfl_xor_sync(0xffffffffu, best[r], off);
                best[r] = umin64(best[r], o);
            }
        }
        if (l == 0) {
            #pragma unroll
            for (int r = 0; r < 8; r++) {
                int bi = (int)(best[r] & 0xffffffffull);
                sbidx[8 * w + r] = bi;
                out[OFF_IDX + tile * ROWT + 8 * w + r] = (float)bi;
                atomicAdd(&g_cs[bi], 1.0f);
            }
        }
        __syncthreads();

        // --- epilogue: quantized gather, loss, dw scatter ---
        #pragma unroll
        for (int i = 0; i < 4; i++) {
            int c   = t + TPB * i;
            int row = c & 63;
            int d4  = (c >> 6) * 4;
            int bi  = sbidx[row];
            float q0 = es[(d4 + 0) * KK + bi];
            float q1 = es[(d4 + 1) * KK + bi];
            float q2 = es[(d4 + 2) * KK + bi];
            float q3 = es[(d4 + 3) * KK + bi];
            float x0 = xs[(d4 + 0) * XS + row];
            float x1 = xs[(d4 + 1) * XS + row];
            float x2 = xs[(d4 + 2) * XS + row];
            float x3 = xs[(d4 + 3) * XS + row];
            float e0 = q0 - x0, e1 = q1 - x1, e2 = q2 - x2, e3 = q3 - x3;
            lacc = fmaf(e0, e0, lacc); lacc = fmaf(e1, e1, lacc);
            lacc = fmaf(e2, e2, lacc); lacc = fmaf(e3, e3, lacc);
            *(float4*)(out + OFF_Q + (size_t)(tile * ROWT + row) * DD + d4)
                = make_float4(q0, q1, q2, q3);
            atomicAdd(&g_dw[(d4 + 0) * KK + bi], x0);
            atomicAdd(&g_dw[(d4 + 1) * KK + bi], x1);
            atomicAdd(&g_dw[(d4 + 2) * KK + bi], x2);
            atomicAdd(&g_dw[(d4 + 3) * KK + bi], x3);
        }
        __syncthreads();
    }

    // loss: warp-reduce then one atomic per warp
    #pragma unroll
    for (int off = 16; off; off >>= 1)
        lacc += __shfl_down_sync(0xffffffffu, lacc, off);
    if (l == 0 && lacc != 0.0f) atomicAdd(&g_loss, lacc);
}

// --- epilogue part 1: per-code stats, fp32 fast path (1 block, 512 threads) ---
__global__ void k_fin1(const float* __restrict__ ema_cs,
                       const int* __restrict__ counter,
                       float* __restrict__ out)
{
    __shared__ float s_part[16];
    __shared__ float s_bcast[2];           // [0]=inv_debias, [1]=reduced scalar
    const int t = threadIdx.x;             // 512 == KK
    const int w = t >> 5, l = t & 31;

    if (t == 0) {
        double db = 1.0 - pow(0.99, (double)(counter[0] + 1));
        float invdb = (float)(1.0 / db);
        s_bcast[0] = invdb;
        g_inv_debias = invdb;
        out[OFF_LOSS] = 0.25f * (g_loss / (float)(NV * DD));
        g_loss = 0.0f;
    }
    __syncthreads();
    const float inv_db = s_bcast[0];

    float cs  = g_cs[t];
    g_cs[t] = 0.0f;                        // restore scratch
    float hid = ema_cs[t] * DECAYF + cs * (1.0f - DECAYF);
    out[OFF_HIDCS + t] = hid;
    float upd = hid * inv_db;

    // nsum = sum(upd)
    float v = upd;
    #pragma unroll
    for (int off = 16; off; off >>= 1) v += __shfl_xor_sync(0xffffffffu, v, off);
    if (l == 0) s_part[w] = v;
    __syncthreads();
    if (t < 32) {
        float pv = (t < 16) ? s_part[t] : 0.0f;
        #pragma unroll
        for (int off = 8; off; off >>= 1) pv += __shfl_xor_sync(0xffffffffu, pv, off);
        if (t == 0) s_bcast[1] = pv;
    }
    __syncthreads();
    const float nsum = s_bcast[1];

    float stable = ((upd + EPSF) / (nsum + (float)KK * EPSF)) * nsum;
    g_inv_stable[t] = 1.0f / stable;

    // entropy -> perplexity
    float p = cs * (1.0f / (float)NV);
    float e = -p * logf(p + 1e-10f);
    #pragma unroll
    for (int off = 16; off; off >>= 1) e += __shfl_xor_sync(0xffffffffu, e, off);
    if (l == 0) s_part[w] = e;
    __syncthreads();
    if (t < 32) {
        float pv = (t < 16) ? s_part[t] : 0.0f;
        #pragma unroll
        for (int off = 8; off; off >>= 1) pv += __shfl_xor_sync(0xffffffffu, pv, off);
        if (t == 0) out[OFF_PERP] = expf(pv);
    }
}

// --- epilogue part 2: 32K-element elementwise map, fp32 only, many blocks ---
__global__ void k_fin2(const float* __restrict__ ema_dw,
                       float* __restrict__ out)
{
    int i = blockIdx.x * blockDim.x + threadIdx.x;   // 64 x 512 = 32768
    float inv_deb = g_inv_debias;
    float dwv = g_dw[i];
    g_dw[i] = 0.0f;                       // restore scratch
    float hdw = ema_dw[i] * DECAYF + dwv * (1.0f - DECAYF);
    out[OFF_HIDDW + i] = hdw;
    out[OFF_NEWEMB + i] = (hdw * inv_deb) * g_inv_stable[i & (KK - 1)];
}

extern "C" void kernel_launch(void* const* d_in, const int* in_sizes, int n_in,
                              void* d_out, int out_size)
{
    const float* x       = (const float*)d_in[0];
    const float* emb     = (const float*)d_in[1];
    const float* ema_cs  = (const float*)d_in[2];
    const float* ema_dw  = (const float*)d_in[3];
    const int*   counter = (const int*)d_in[4];
    float* out = (float*)d_out;

    const int smem = (DD * KK + KK + DD * XS) * (int)sizeof(float)
                   + ROWT * (int)sizeof(int);        // 150,784 B
    cudaFuncSetAttribute(k_main, cudaFuncAttributeMaxDynamicSharedMemorySize, smem);

    k_main<<<GRID, TPB, smem>>>(x, emb, out);
    k_fin1<<<1, KK>>>(ema_cs, counter, out);
    k_fin2<<<64, 512>>>(ema_dw, out);
}